// round 10
// baseline (speedup 1.0000x reference)
#include <cuda_runtime.h>
#include <cuda_fp16.h>
#include <cstdint>
#include <math.h>

#define S_IMG 16384
#define N_TXT 4096
#define DIM   512

// ---------------- scratch (static device globals; no allocations) ----------------
__device__ __half g_zimg_h[(size_t)S_IMG * DIM];  // fp16 zimg
__device__ __half g_ztxt_h[(size_t)N_TXT * DIM];  // fp16 ztxt
__device__ float  g_loss[S_IMG];
__device__ int    g_segmin[N_TXT];
__device__ int    g_sel[N_TXT];
__device__ float  g_rowsum[N_TXT];

// ---------------- streams/events: created at program load; reused every call ----
static cudaStream_t g_side;
static cudaEvent_t  g_fork, g_join;
struct _StreamInit {
    _StreamInit() {
        cudaStreamCreateWithFlags(&g_side, cudaStreamNonBlocking);
        cudaEventCreateWithFlags(&g_fork, cudaEventDisableTiming);
        cudaEventCreateWithFlags(&g_join, cudaEventDisableTiming);
    }
};
static _StreamInit g_si;

// ---------------- L2 normalize: exact fp32 to d_out (scalar, 4B-aligned only),
// fp16 copy to scratch; txt blocks also init segmin/sel (replaces init_kernel) ----
__global__ void norm_kernel(const float* __restrict__ src, float* __restrict__ dst, int which) {
    int row = blockIdx.x;
    int tid = threadIdx.x;  // 128 threads, each one float4 (512 elems)
    __half* dst_h = which ? g_ztxt_h : g_zimg_h;
    if (which && tid == 0) { g_segmin[row] = 0x7F800000; g_sel[row] = S_IMG; }
    float4 v = reinterpret_cast<const float4*>(src + (size_t)row * DIM)[tid];
    float p = v.x * v.x + v.y * v.y + v.z * v.z + v.w * v.w;
#pragma unroll
    for (int o = 16; o; o >>= 1) p += __shfl_down_sync(0xffffffffu, p, o);
    __shared__ float ws[4];
    __shared__ float nshared;
    if ((tid & 31) == 0) ws[tid >> 5] = p;
    __syncthreads();
    if (tid == 0) nshared = sqrtf(ws[0] + ws[1] + ws[2] + ws[3]) + 1e-12f;
    __syncthreads();
    float n = nshared;
    float4 o;
    o.x = v.x / n; o.y = v.y / n; o.z = v.z / n; o.w = v.w / n;
    float* drow = dst + (size_t)row * DIM + tid * 4;
    drow[0] = o.x; drow[1] = o.y; drow[2] = o.z; drow[3] = o.w;
    __half2* hp = reinterpret_cast<__half2*>(dst_h + (size_t)row * DIM);
    hp[tid * 2]     = __floats2half2_rn(o.x, o.y);
    hp[tid * 2 + 1] = __floats2half2_rn(o.z, o.w);
}

// ---------------- exact fp32 true-positive logits + segment-min -----------------
__global__ void tp_kernel(const float* __restrict__ zimg, const float* __restrict__ ztxt,
                          const int* __restrict__ key, const float* __restrict__ logt,
                          const float* __restrict__ bias) {
    int gw = (blockIdx.x * blockDim.x + threadIdx.x) >> 5;
    int lane = threadIdx.x & 31;
    if (gw >= S_IMG) return;
    int k = key[gw];
    const float* a = zimg + (size_t)gw * DIM;
    const float* b = ztxt + (size_t)k * DIM;
    float s = 0.f;
#pragma unroll
    for (int j = 0; j < DIM / 32; j++) s = fmaf(a[lane + j * 32], b[lane + j * 32], s);
#pragma unroll
    for (int o = 16; o; o >>= 1) s += __shfl_down_sync(0xffffffffu, s, o);
    if (lane == 0) {
        float t = expf(logt[0]);
        float tpl = fmaf(s, t, bias[0]);
        float x = -tpl;
        float loss = fmaxf(x, 0.f) + log1pf(expf(-fabsf(x)));
        g_loss[gw] = loss;
        atomicMin(&g_segmin[k], __float_as_int(loss));  // loss >= 0 -> bit order ok
    }
}

__global__ void pick_kernel(const int* __restrict__ key) {
    int i = blockIdx.x * blockDim.x + threadIdx.x;
    if (i < S_IMG) {
        int k = key[i];
        if (__float_as_int(g_loss[i]) == g_segmin[k]) atomicMin(&g_sel[k], i);
    }
}

__global__ void sel_kernel(float* __restrict__ out_idx) {
    int j = blockIdx.x * blockDim.x + threadIdx.x;
    if (j < N_TXT) {
        int sel = g_sel[j];
        out_idx[j] = (sel < S_IMG) ? (float)sel : -1.0f;
    }
}

// ---------------- fp16 mma.sync GEMM: 4 warps, warp tile 64x64 -------------------
#define BM 128
#define BN 128
#define BKH 64                                  // fp16 k per stage
#define NSTG (DIM / BKH)                        // 8
#define LDHB 144                                // bytes per smem row (64 fp16 + 8 pad)
#define AREG (BM * LDHB)                        // 18432
#define STAGE_BYTES (2 * AREG)                  // 36864 (A + B)
#define GSMEM_BYTES (2 * STAGE_BYTES)           // 73728 double-buffered

__device__ __forceinline__ uint32_t smem_u32(const void* p) {
    uint32_t a;
    asm("{ .reg .u64 t; cvta.to.shared.u64 t, %1; cvt.u32.u64 %0, t; }" : "=r"(a) : "l"(p));
    return a;
}
__device__ __forceinline__ void cp16(void* s, const void* g) {
    uint32_t sa = smem_u32(s);
    asm volatile("cp.async.cg.shared.global [%0], [%1], 16;\n" ::"r"(sa), "l"(g) : "memory");
}
#define LDSM4(r0, r1, r2, r3, addr)                                            \
    asm volatile("ldmatrix.sync.aligned.m8n8.x4.shared.b16 {%0,%1,%2,%3}, [%4];" \
                 : "=r"(r0), "=r"(r1), "=r"(r2), "=r"(r3) : "r"(addr))

__device__ __forceinline__ void mmaf16(float* d, const uint32_t* a, const uint32_t* b) {
    asm volatile(
        "mma.sync.aligned.m16n8k16.row.col.f32.f16.f16.f32 "
        "{%0,%1,%2,%3}, {%4,%5,%6,%7}, {%8,%9}, {%0,%1,%2,%3};\n"
        : "+f"(d[0]), "+f"(d[1]), "+f"(d[2]), "+f"(d[3])
        : "r"(a[0]), "r"(a[1]), "r"(a[2]), "r"(a[3]), "r"(b[0]), "r"(b[1]));
}

__global__ __launch_bounds__(128, 2) void gemm_kernel(float* __restrict__ C,
                                                      const float* __restrict__ logt,
                                                      const float* __restrict__ bias) {
    extern __shared__ __align__(128) char smem[];
    uint32_t sb = smem_u32(smem);
    const __half* A = g_zimg_h;
    const __half* B = g_ztxt_h;
    int tid = threadIdx.x;
    int lane = tid & 31, warp = tid >> 5;
    int wm = warp >> 1, wn = warp & 1;  // 2x2 warp grid; warp tile 64x64
    size_t m0 = (size_t)blockIdx.y * BM;
    size_t n0 = (size_t)blockIdx.x * BN;

    float acc[4][8][4];
#pragma unroll
    for (int i = 0; i < 4; i++)
#pragma unroll
        for (int j = 0; j < 8; j++)
#pragma unroll
            for (int r = 0; r < 4; r++) acc[i][j][r] = 0.f;

    // per-stage loader: 128 threads, A: 128 rows x 8 chunks, B same
    auto load_stage = [&](int s) {
        char* st = smem + (s & 1) * STAGE_BYTES;
        int kof = s * BKH;
#pragma unroll
        for (int i = 0; i < 8; i++) {
            int e = tid + i * 128;
            int r = e >> 3, c = e & 7;
            cp16(st + r * LDHB + c * 16, A + (m0 + r) * DIM + kof + c * 8);
        }
        char* stb = st + AREG;
#pragma unroll
        for (int i = 0; i < 8; i++) {
            int e = tid + i * 128;
            int r = e >> 3, c = e & 7;
            cp16(stb + r * LDHB + c * 16, B + (n0 + r) * DIM + kof + c * 8);
        }
        asm volatile("cp.async.commit_group;\n" ::: "memory");
    };

    load_stage(0);
    load_stage(1);

    int lrow = lane & 7;
    int aRow = ((lane >> 3) & 1) * 8 + lrow;   // row within 16
    int aColB = (lane >> 4) * 16;              // byte offset of k-half
    int bRow = (lane >> 4) * 8 + lrow;
    int bColB = ((lane >> 3) & 1) * 16;

    for (int kt = 0; kt < NSTG; kt++) {
        if (kt < NSTG - 1) asm volatile("cp.async.wait_group 1;" ::: "memory");
        else               asm volatile("cp.async.wait_group 0;" ::: "memory");
        __syncthreads();

        uint32_t base = sb + (kt & 1) * STAGE_BYTES;
        uint32_t baseA = base + (wm * 64 + aRow) * LDHB + aColB;
        uint32_t baseB = base + AREG + (wn * 64 + bRow) * LDHB + bColB;
#pragma unroll
        for (int ks = 0; ks < BKH / 16; ks++) {
            uint32_t kb = ks * 32;  // 16 fp16 = 32 bytes
            uint32_t af[4][4], bf[8][2];
#pragma unroll
            for (int mi = 0; mi < 4; mi++)
                LDSM4(af[mi][0], af[mi][1], af[mi][2], af[mi][3],
                      baseA + mi * 16 * LDHB + kb);
#pragma unroll
            for (int p = 0; p < 4; p++)
                LDSM4(bf[2 * p][0], bf[2 * p][1], bf[2 * p + 1][0], bf[2 * p + 1][1],
                      baseB + p * 16 * LDHB + kb);
#pragma unroll
            for (int mi = 0; mi < 4; mi++)
#pragma unroll
                for (int ni = 0; ni < 8; ni++) mmaf16(acc[mi][ni], af[mi], bf[ni]);
        }
        __syncthreads();
        if (kt + 2 < NSTG) load_stage(kt + 2);
    }

    float t = expf(logt[0]);
    float bb = bias[0];
#pragma unroll
    for (int mi = 0; mi < 4; mi++)
#pragma unroll
        for (int ni = 0; ni < 8; ni++) {
            size_t row = m0 + wm * 64 + mi * 16 + (lane >> 2);
            size_t col = n0 + wn * 64 + ni * 8 + (size_t)(lane & 3) * 2;
            float* p0 = C + row * N_TXT + col;          // scalar: d_out 4B-aligned
            float* p1 = C + (row + 8) * N_TXT + col;
            p0[0] = fmaf(acc[mi][ni][0], t, bb);
            p0[1] = fmaf(acc[mi][ni][1], t, bb);
            p1[0] = fmaf(acc[mi][ni][2], t, bb);
            p1[1] = fmaf(acc[mi][ni][3], t, bb);
        }
}

// ---------------- fused gather + row loss ----------------------------------------
__global__ void gather_fl_kernel(const float* __restrict__ AP, float* __restrict__ FL,
                                 const float* __restrict__ bias) {
    int j = blockIdx.x;
    int sel = g_sel[j];
    bool valid = sel < S_IMG;
    const float* src = AP + (size_t)(valid ? sel : 0) * N_TXT;
    float bb = bias[0];
    float* dst = FL + (size_t)j * N_TXT;
    float s = 0.f;
    for (int c = threadIdx.x; c < N_TXT; c += blockDim.x) {
        float x = valid ? src[c] : bb;
        dst[c] = x;
        float z = (c == j) ? -x : x;  // softplus(-(label*x)), label = 2*eye-1
        s += fmaxf(z, 0.f) + __logf(1.f + __expf(-fabsf(z)));
    }
#pragma unroll
    for (int o = 16; o; o >>= 1) s += __shfl_down_sync(0xffffffffu, s, o);
    __shared__ float sm[8];
    if ((threadIdx.x & 31) == 0) sm[threadIdx.x >> 5] = s;
    __syncthreads();
    if (threadIdx.x == 0) {
        float tot = 0.f;
#pragma unroll
        for (int w = 0; w < 8; w++) tot += sm[w];
        g_rowsum[j] = tot;
    }
}

__global__ void finalize_kernel(float* __restrict__ out) {
    int tid = threadIdx.x;
    double s = 0.0;
    for (int i = tid; i < N_TXT; i += 256) s += (double)g_rowsum[i];
#pragma unroll
    for (int o = 16; o; o >>= 1) s += __shfl_down_sync(0xffffffffu, s, o);
    __shared__ double sm[8];
    if ((tid & 31) == 0) sm[tid >> 5] = s;
    __syncthreads();
    if (tid == 0) {
        double tot = 0.0;
#pragma unroll
        for (int w = 0; w < 8; w++) tot += sm[w];
        out[0] = (float)(tot / (double)N_TXT);
    }
}

// ---------------- launch ---------------------------------------------------------
extern "C" void kernel_launch(void* const* d_in, const int* in_sizes, int n_in,
                              void* d_out, int out_size) {
    const float* img  = (const float*)d_in[0];
    const float* txt  = (const float*)d_in[1];
    const int*   key  = (const int*)d_in[2];
    const float* logt = (const float*)d_in[3];
    const float* bias = (const float*)d_in[4];

    float* out      = (float*)d_out;
    float* out_loss = out;                                   // [1]
    float* out_sel  = out + 1;                               // [4096]
    float* out_zimg = out_sel + N_TXT;                       // [16384*512]
    float* out_ztxt = out_zimg + (size_t)S_IMG * DIM;        // [4096*512]
    float* out_ap   = out_ztxt + (size_t)N_TXT * DIM;        // [16384*4096]
    float* out_fl   = out_ap + (size_t)S_IMG * N_TXT;        // [4096*4096]

    cudaFuncSetAttribute(gemm_kernel, cudaFuncAttributeMaxDynamicSharedMemorySize, GSMEM_BYTES);

    // main stream: normalize (feeds both branches; txt blocks also init segmin/sel)
    norm_kernel<<<S_IMG, 128>>>(img, out_zimg, 0);
    norm_kernel<<<N_TXT, 128>>>(txt, out_ztxt, 1);

    // fork: cheap exact-fp32 selection chain on side stream (hides under GEMM1)
    cudaEventRecord(g_fork, 0);
    cudaStreamWaitEvent(g_side, g_fork, 0);
    tp_kernel<<<S_IMG / 8, 256, 0, g_side>>>(out_zimg, out_ztxt, key, logt, bias);
    pick_kernel<<<S_IMG / 256, 256, 0, g_side>>>(key);
    sel_kernel<<<(N_TXT + 255) / 256, 256, 0, g_side>>>(out_sel);
    cudaEventRecord(g_join, g_side);

    // main stream: big GEMM (all_pairs_logits [16384, 4096])
    gemm_kernel<<<dim3(N_TXT / BN, S_IMG / BM), 128, GSMEM_BYTES>>>(out_ap, logt, bias);

    // join, then final_logits = row-gather of all_pairs (fused with row loss)
    cudaStreamWaitEvent(0, g_join, 0);
    gather_fl_kernel<<<N_TXT, 256>>>(out_ap, out_fl, bias);
    finalize_kernel<<<1, 256>>>(out_loss);
}

// round 11
// speedup vs baseline: 1.0019x; 1.0019x over previous
#include <cuda_runtime.h>
#include <cuda_fp16.h>
#include <cstdint>
#include <math.h>

#define S_IMG 16384
#define N_TXT 4096
#define DIM   512

// ---------------- scratch (static device globals; no allocations) ----------------
__device__ __half g_zimg_h[(size_t)S_IMG * DIM];  // fp16 zimg
__device__ __half g_ztxt_h[(size_t)N_TXT * DIM];  // fp16 ztxt
__device__ float  g_loss[S_IMG];
__device__ int    g_segmin[N_TXT];
__device__ int    g_sel[N_TXT];
__device__ float  g_rowsum[N_TXT];

// ---------------- streams/events: created at program load; reused every call ----
static cudaStream_t g_side;
static cudaEvent_t  g_fork, g_join;
struct _StreamInit {
    _StreamInit() {
        cudaStreamCreateWithFlags(&g_side, cudaStreamNonBlocking);
        cudaEventCreateWithFlags(&g_fork, cudaEventDisableTiming);
        cudaEventCreateWithFlags(&g_join, cudaEventDisableTiming);
    }
};
static _StreamInit g_si;

// ---------------- L2 normalize: exact fp32 to d_out (scalar, 4B-aligned only),
// fp16 copy to scratch; txt blocks also init segmin/sel ---------------------------
__global__ void norm_kernel(const float* __restrict__ src, float* __restrict__ dst, int which) {
    int row = blockIdx.x;
    int tid = threadIdx.x;  // 128 threads, each one float4 (512 elems)
    __half* dst_h = which ? g_ztxt_h : g_zimg_h;
    if (which && tid == 0) { g_segmin[row] = 0x7F800000; g_sel[row] = S_IMG; }
    float4 v = reinterpret_cast<const float4*>(src + (size_t)row * DIM)[tid];
    float p = v.x * v.x + v.y * v.y + v.z * v.z + v.w * v.w;
#pragma unroll
    for (int o = 16; o; o >>= 1) p += __shfl_down_sync(0xffffffffu, p, o);
    __shared__ float ws[4];
    __shared__ float nshared;
    if ((tid & 31) == 0) ws[tid >> 5] = p;
    __syncthreads();
    if (tid == 0) nshared = sqrtf(ws[0] + ws[1] + ws[2] + ws[3]) + 1e-12f;
    __syncthreads();
    float n = nshared;
    float4 o;
    o.x = v.x / n; o.y = v.y / n; o.z = v.z / n; o.w = v.w / n;
    float* drow = dst + (size_t)row * DIM + tid * 4;
    drow[0] = o.x; drow[1] = o.y; drow[2] = o.z; drow[3] = o.w;
    __half2* hp = reinterpret_cast<__half2*>(dst_h + (size_t)row * DIM);
    hp[tid * 2]     = __floats2half2_rn(o.x, o.y);
    hp[tid * 2 + 1] = __floats2half2_rn(o.z, o.w);
}

// ---------------- exact fp32 true-positive logits + segment-min -----------------
__global__ void tp_kernel(const float* __restrict__ zimg, const float* __restrict__ ztxt,
                          const int* __restrict__ key, const float* __restrict__ logt,
                          const float* __restrict__ bias) {
    int gw = (blockIdx.x * blockDim.x + threadIdx.x) >> 5;
    int lane = threadIdx.x & 31;
    if (gw >= S_IMG) return;
    int k = key[gw];
    const float* a = zimg + (size_t)gw * DIM;
    const float* b = ztxt + (size_t)k * DIM;
    float s = 0.f;
#pragma unroll
    for (int j = 0; j < DIM / 32; j++) s = fmaf(a[lane + j * 32], b[lane + j * 32], s);
#pragma unroll
    for (int o = 16; o; o >>= 1) s += __shfl_down_sync(0xffffffffu, s, o);
    if (lane == 0) {
        float t = expf(logt[0]);
        float tpl = fmaf(s, t, bias[0]);
        float x = -tpl;
        float loss = fmaxf(x, 0.f) + log1pf(expf(-fabsf(x)));
        g_loss[gw] = loss;
        atomicMin(&g_segmin[k], __float_as_int(loss));  // loss >= 0 -> bit order ok
    }
}

__global__ void pick_kernel(const int* __restrict__ key) {
    int i = blockIdx.x * blockDim.x + threadIdx.x;
    if (i < S_IMG) {
        int k = key[i];
        if (__float_as_int(g_loss[i]) == g_segmin[k]) atomicMin(&g_sel[k], i);
    }
}

__global__ void sel_kernel(float* __restrict__ out_idx) {
    int j = blockIdx.x * blockDim.x + threadIdx.x;
    if (j < N_TXT) {
        int sel = g_sel[j];
        out_idx[j] = (sel < S_IMG) ? (float)sel : -1.0f;
    }
}

// ---------------- fp16 mma.sync GEMM: block 128x64, 8 warps of 32x32, 3 CTA/SM ---
#define BM 128
#define BN 64
#define BKH 64                                  // fp16 k per stage
#define NSTG (DIM / BKH)                        // 8
#define LDHB 144                                // bytes per smem row (64 fp16 + 8 pad)
#define AREG (BM * LDHB)                        // 18432
#define BREG (BN * LDHB)                        // 9216
#define STAGE_BYTES (AREG + BREG)               // 27648
#define GSMEM_BYTES (2 * STAGE_BYTES)           // 55296 double-buffered

__device__ __forceinline__ uint32_t smem_u32(const void* p) {
    uint32_t a;
    asm("{ .reg .u64 t; cvta.to.shared.u64 t, %1; cvt.u32.u64 %0, t; }" : "=r"(a) : "l"(p));
    return a;
}
__device__ __forceinline__ void cp16(void* s, const void* g) {
    uint32_t sa = smem_u32(s);
    asm volatile("cp.async.cg.shared.global [%0], [%1], 16;\n" ::"r"(sa), "l"(g) : "memory");
}
#define LDSM4(r0, r1, r2, r3, addr)                                            \
    asm volatile("ldmatrix.sync.aligned.m8n8.x4.shared.b16 {%0,%1,%2,%3}, [%4];" \
                 : "=r"(r0), "=r"(r1), "=r"(r2), "=r"(r3) : "r"(addr))

__device__ __forceinline__ void mmaf16(float* d, const uint32_t* a, const uint32_t* b) {
    asm volatile(
        "mma.sync.aligned.m16n8k16.row.col.f32.f16.f16.f32 "
        "{%0,%1,%2,%3}, {%4,%5,%6,%7}, {%8,%9}, {%0,%1,%2,%3};\n"
        : "+f"(d[0]), "+f"(d[1]), "+f"(d[2]), "+f"(d[3])
        : "r"(a[0]), "r"(a[1]), "r"(a[2]), "r"(a[3]), "r"(b[0]), "r"(b[1]));
}

__global__ __launch_bounds__(256, 3) void gemm_kernel(float* __restrict__ C,
                                                      const float* __restrict__ logt,
                                                      const float* __restrict__ bias) {
    extern __shared__ __align__(128) char smem[];
    uint32_t sb = smem_u32(smem);
    const __half* A = g_zimg_h;
    const __half* B = g_ztxt_h;
    int tid = threadIdx.x;
    int lane = tid & 31, warp = tid >> 5;
    int wm = warp >> 1, wn = warp & 1;  // 4x2 warp grid; warp tile 32x32
    size_t m0 = (size_t)blockIdx.y * BM;
    size_t n0 = (size_t)blockIdx.x * BN;

    float acc[2][4][4];
#pragma unroll
    for (int i = 0; i < 2; i++)
#pragma unroll
        for (int j = 0; j < 4; j++)
#pragma unroll
            for (int r = 0; r < 4; r++) acc[i][j][r] = 0.f;

    // per-stage loader: A 128 rows x 8 chunks (4/thread), B 64 rows x 8 (2/thread)
    auto load_stage = [&](int s) {
        char* st = smem + (s & 1) * STAGE_BYTES;
        int kof = s * BKH;
#pragma unroll
        for (int i = 0; i < 4; i++) {
            int e = tid + i * 256;
            int r = e >> 3, c = e & 7;
            cp16(st + r * LDHB + c * 16, A + (m0 + r) * DIM + kof + c * 8);
        }
        char* stb = st + AREG;
#pragma unroll
        for (int i = 0; i < 2; i++) {
            int e = tid + i * 256;
            int r = e >> 3, c = e & 7;
            cp16(stb + r * LDHB + c * 16, B + (n0 + r) * DIM + kof + c * 8);
        }
        asm volatile("cp.async.commit_group;\n" ::: "memory");
    };

    load_stage(0);
    load_stage(1);

    int lrow = lane & 7;
    int aRow = ((lane >> 3) & 1) * 8 + lrow;   // row within 16
    int aColB = (lane >> 4) * 16;              // byte offset of k-half
    int bRow = (lane >> 4) * 8 + lrow;
    int bColB = ((lane >> 3) & 1) * 16;

    for (int kt = 0; kt < NSTG; kt++) {
        if (kt < NSTG - 1) asm volatile("cp.async.wait_group 1;" ::: "memory");
        else               asm volatile("cp.async.wait_group 0;" ::: "memory");
        __syncthreads();

        uint32_t base = sb + (kt & 1) * STAGE_BYTES;
        uint32_t baseA = base + (wm * 32 + aRow) * LDHB + aColB;
        uint32_t baseB = base + AREG + (wn * 32 + bRow) * LDHB + bColB;
#pragma unroll
        for (int ks = 0; ks < BKH / 16; ks++) {
            uint32_t kb = ks * 32;  // 16 fp16 = 32 bytes
            uint32_t af[2][4], bf[4][2];
#pragma unroll
            for (int mi = 0; mi < 2; mi++)
                LDSM4(af[mi][0], af[mi][1], af[mi][2], af[mi][3],
                      baseA + mi * 16 * LDHB + kb);
#pragma unroll
            for (int p = 0; p < 2; p++)
                LDSM4(bf[2 * p][0], bf[2 * p][1], bf[2 * p + 1][0], bf[2 * p + 1][1],
                      baseB + p * 16 * LDHB + kb);
#pragma unroll
            for (int mi = 0; mi < 2; mi++)
#pragma unroll
                for (int ni = 0; ni < 4; ni++) mmaf16(acc[mi][ni], af[mi], bf[ni]);
        }
        __syncthreads();
        if (kt + 2 < NSTG) load_stage(kt + 2);
    }

    float t = expf(logt[0]);
    float bb = bias[0];
#pragma unroll
    for (int mi = 0; mi < 2; mi++)
#pragma unroll
        for (int ni = 0; ni < 4; ni++) {
            size_t row = m0 + wm * 32 + mi * 16 + (lane >> 2);
            size_t col = n0 + wn * 32 + ni * 8 + (size_t)(lane & 3) * 2;
            float* p0 = C + row * N_TXT + col;          // scalar: d_out 4B-aligned
            float* p1 = C + (row + 8) * N_TXT + col;
            p0[0] = fmaf(acc[mi][ni][0], t, bb);
            p0[1] = fmaf(acc[mi][ni][1], t, bb);
            p1[0] = fmaf(acc[mi][ni][2], t, bb);
            p1[1] = fmaf(acc[mi][ni][3], t, bb);
        }
}

// ---------------- fused gather + row loss ----------------------------------------
__global__ void gather_fl_kernel(const float* __restrict__ AP, float* __restrict__ FL,
                                 const float* __restrict__ bias) {
    int j = blockIdx.x;
    int sel = g_sel[j];
    bool valid = sel < S_IMG;
    const float* src = AP + (size_t)(valid ? sel : 0) * N_TXT;
    float bb = bias[0];
    float* dst = FL + (size_t)j * N_TXT;
    float s = 0.f;
    for (int c = threadIdx.x; c < N_TXT; c += blockDim.x) {
        float x = valid ? src[c] : bb;
        dst[c] = x;
        float z = (c == j) ? -x : x;  // softplus(-(label*x)), label = 2*eye-1
        s += fmaxf(z, 0.f) + __logf(1.f + __expf(-fabsf(z)));
    }
#pragma unroll
    for (int o = 16; o; o >>= 1) s += __shfl_down_sync(0xffffffffu, s, o);
    __shared__ float sm[8];
    if ((threadIdx.x & 31) == 0) sm[threadIdx.x >> 5] = s;
    __syncthreads();
    if (threadIdx.x == 0) {
        float tot = 0.f;
#pragma unroll
        for (int w = 0; w < 8; w++) tot += sm[w];
        g_rowsum[j] = tot;
    }
}

__global__ void finalize_kernel(float* __restrict__ out) {
    int tid = threadIdx.x;
    double s = 0.0;
    for (int i = tid; i < N_TXT; i += 256) s += (double)g_rowsum[i];
#pragma unroll
    for (int o = 16; o; o >>= 1) s += __shfl_down_sync(0xffffffffu, s, o);
    __shared__ double sm[8];
    if ((tid & 31) == 0) sm[tid >> 5] = s;
    __syncthreads();
    if (tid == 0) {
        double tot = 0.0;
#pragma unroll
        for (int w = 0; w < 8; w++) tot += sm[w];
        out[0] = (float)(tot / (double)N_TXT);
    }
}

// ---------------- launch ---------------------------------------------------------
extern "C" void kernel_launch(void* const* d_in, const int* in_sizes, int n_in,
                              void* d_out, int out_size) {
    const float* img  = (const float*)d_in[0];
    const float* txt  = (const float*)d_in[1];
    const int*   key  = (const int*)d_in[2];
    const float* logt = (const float*)d_in[3];
    const float* bias = (const float*)d_in[4];

    float* out      = (float*)d_out;
    float* out_loss = out;                                   // [1]
    float* out_sel  = out + 1;                               // [4096]
    float* out_zimg = out_sel + N_TXT;                       // [16384*512]
    float* out_ztxt = out_zimg + (size_t)S_IMG * DIM;        // [4096*512]
    float* out_ap   = out_ztxt + (size_t)N_TXT * DIM;        // [16384*4096]
    float* out_fl   = out_ap + (size_t)S_IMG * N_TXT;        // [4096*4096]

    cudaFuncSetAttribute(gemm_kernel, cudaFuncAttributeMaxDynamicSharedMemorySize, GSMEM_BYTES);

    // main stream: normalize (feeds both branches; txt blocks also init segmin/sel)
    norm_kernel<<<S_IMG, 128>>>(img, out_zimg, 0);
    norm_kernel<<<N_TXT, 128>>>(txt, out_ztxt, 1);

    // fork: cheap exact-fp32 selection chain on side stream (hides under GEMM1)
    cudaEventRecord(g_fork, 0);
    cudaStreamWaitEvent(g_side, g_fork, 0);
    tp_kernel<<<S_IMG / 8, 256, 0, g_side>>>(out_zimg, out_ztxt, key, logt, bias);
    pick_kernel<<<S_IMG / 256, 256, 0, g_side>>>(key);
    sel_kernel<<<(N_TXT + 255) / 256, 256, 0, g_side>>>(out_sel);
    cudaEventRecord(g_join, g_side);

    // main stream: big GEMM (all_pairs_logits [16384, 4096])
    gemm_kernel<<<dim3(N_TXT / BN, S_IMG / BM), 256, GSMEM_BYTES>>>(out_ap, logt, bias);

    // join, then final_logits = row-gather of all_pairs (fused with row loss)
    cudaStreamWaitEvent(0, g_join, 0);
    gather_fl_kernel<<<N_TXT, 256>>>(out_ap, out_fl, bias);
    finalize_kernel<<<1, 256>>>(out_loss);
}

// round 12
// speedup vs baseline: 1.0543x; 1.0523x over previous
#include <cuda_runtime.h>
#include <cuda_fp16.h>
#include <cstdint>
#include <math.h>

#define S_IMG 16384
#define N_TXT 4096
#define DIM   512

// ---------------- scratch (static device globals; no allocations) ----------------
__device__ __half g_zimg_h[(size_t)S_IMG * DIM];  // fp16 zimg
__device__ __half g_ztxt_h[(size_t)N_TXT * DIM];  // fp16 ztxt
__device__ float  g_loss[S_IMG];
__device__ int    g_segmin[N_TXT];
__device__ int    g_sel[N_TXT];
__device__ float  g_rowsum[N_TXT];

// ---------------- streams/events: created at program load; reused every call ----
static cudaStream_t g_side;
static cudaEvent_t  g_fork, g_join;
struct _StreamInit {
    _StreamInit() {
        cudaStreamCreateWithFlags(&g_side, cudaStreamNonBlocking);
        cudaEventCreateWithFlags(&g_fork, cudaEventDisableTiming);
        cudaEventCreateWithFlags(&g_join, cudaEventDisableTiming);
    }
};
static _StreamInit g_si;

// ---------------- L2 normalize (img+txt in ONE launch): exact fp32 to d_out
// (scalar stores; d_out only 4B-aligned), fp16 copy to scratch; txt rows also
// init segmin/sel ----------------------------------------------------------------
__global__ void norm_all_kernel(const float* __restrict__ img, const float* __restrict__ txt,
                                float* __restrict__ dimg, float* __restrict__ dtxt) {
    int row = blockIdx.x;
    int tid = threadIdx.x;  // 128 threads, each one float4 (512 elems)
    bool istxt = row >= S_IMG;
    const float* src;
    float* dst;
    __half* dst_h;
    if (istxt) {
        row -= S_IMG;
        src = txt; dst = dtxt; dst_h = g_ztxt_h;
        if (tid == 0) { g_segmin[row] = 0x7F800000; g_sel[row] = S_IMG; }
    } else {
        src = img; dst = dimg; dst_h = g_zimg_h;
    }
    float4 v = reinterpret_cast<const float4*>(src + (size_t)row * DIM)[tid];
    float p = v.x * v.x + v.y * v.y + v.z * v.z + v.w * v.w;
#pragma unroll
    for (int o = 16; o; o >>= 1) p += __shfl_down_sync(0xffffffffu, p, o);
    __shared__ float ws[4];
    __shared__ float nshared;
    if ((tid & 31) == 0) ws[tid >> 5] = p;
    __syncthreads();
    if (tid == 0) nshared = sqrtf(ws[0] + ws[1] + ws[2] + ws[3]) + 1e-12f;
    __syncthreads();
    float n = nshared;
    float4 o;
    o.x = v.x / n; o.y = v.y / n; o.z = v.z / n; o.w = v.w / n;
    float* drow = dst + (size_t)row * DIM + tid * 4;
    drow[0] = o.x; drow[1] = o.y; drow[2] = o.z; drow[3] = o.w;
    __half2* hp = reinterpret_cast<__half2*>(dst_h + (size_t)row * DIM);
    hp[tid * 2]     = __floats2half2_rn(o.x, o.y);
    hp[tid * 2 + 1] = __floats2half2_rn(o.z, o.w);
}

// ---------------- exact fp32 true-positive logits + segment-min -----------------
__global__ void tp_kernel(const float* __restrict__ zimg, const float* __restrict__ ztxt,
                          const int* __restrict__ key, const float* __restrict__ logt,
                          const float* __restrict__ bias) {
    int gw = (blockIdx.x * blockDim.x + threadIdx.x) >> 5;
    int lane = threadIdx.x & 31;
    if (gw >= S_IMG) return;
    int k = key[gw];
    const float* a = zimg + (size_t)gw * DIM;
    const float* b = ztxt + (size_t)k * DIM;
    float s = 0.f;
#pragma unroll
    for (int j = 0; j < DIM / 32; j++) s = fmaf(a[lane + j * 32], b[lane + j * 32], s);
#pragma unroll
    for (int o = 16; o; o >>= 1) s += __shfl_down_sync(0xffffffffu, s, o);
    if (lane == 0) {
        float t = expf(logt[0]);
        float tpl = fmaf(s, t, bias[0]);
        float x = -tpl;
        float loss = fmaxf(x, 0.f) + log1pf(expf(-fabsf(x)));
        g_loss[gw] = loss;
        atomicMin(&g_segmin[k], __float_as_int(loss));  // loss >= 0 -> bit order ok
    }
}

__global__ void pick_kernel(const int* __restrict__ key) {
    int i = blockIdx.x * blockDim.x + threadIdx.x;
    if (i < S_IMG) {
        int k = key[i];
        if (__float_as_int(g_loss[i]) == g_segmin[k]) atomicMin(&g_sel[k], i);
    }
}

__global__ void sel_kernel(float* __restrict__ out_idx) {
    int j = blockIdx.x * blockDim.x + threadIdx.x;
    if (j < N_TXT) {
        int sel = g_sel[j];
        out_idx[j] = (sel < S_IMG) ? (float)sel : -1.0f;
    }
}

// ---------------- fp16 mma.sync GEMM (R8 shape; 3-stage, 1 barrier/stage) --------
#define BM 128
#define BN 128
#define BKH 64                                  // fp16 k per stage
#define NSTG (DIM / BKH)                        // 8
#define NBUF 3
#define LDHB 144                                // bytes per smem row (64 fp16 + 8 pad)
#define AREG (BM * LDHB)                        // 18432
#define STAGE_BYTES (2 * AREG)                  // 36864 (A + B)
#define GSMEM_BYTES (NBUF * STAGE_BYTES)        // 110592; 2 CTAs = 216KB <= 228KB

__device__ __forceinline__ uint32_t smem_u32(const void* p) {
    uint32_t a;
    asm("{ .reg .u64 t; cvta.to.shared.u64 t, %1; cvt.u32.u64 %0, t; }" : "=r"(a) : "l"(p));
    return a;
}
__device__ __forceinline__ void cp16(void* s, const void* g) {
    uint32_t sa = smem_u32(s);
    asm volatile("cp.async.cg.shared.global [%0], [%1], 16;\n" ::"r"(sa), "l"(g) : "memory");
}
#define LDSM4(r0, r1, r2, r3, addr)                                            \
    asm volatile("ldmatrix.sync.aligned.m8n8.x4.shared.b16 {%0,%1,%2,%3}, [%4];" \
                 : "=r"(r0), "=r"(r1), "=r"(r2), "=r"(r3) : "r"(addr))

__device__ __forceinline__ void mmaf16(float* d, const uint32_t* a, const uint32_t* b) {
    asm volatile(
        "mma.sync.aligned.m16n8k16.row.col.f32.f16.f16.f32 "
        "{%0,%1,%2,%3}, {%4,%5,%6,%7}, {%8,%9}, {%0,%1,%2,%3};\n"
        : "+f"(d[0]), "+f"(d[1]), "+f"(d[2]), "+f"(d[3])
        : "r"(a[0]), "r"(a[1]), "r"(a[2]), "r"(a[3]), "r"(b[0]), "r"(b[1]));
}

__global__ __launch_bounds__(256, 2) void gemm_kernel(float* __restrict__ C,
                                                      const float* __restrict__ logt,
                                                      const float* __restrict__ bias) {
    extern __shared__ __align__(128) char smem[];
    uint32_t sb = smem_u32(smem);
    const __half* A = g_zimg_h;
    const __half* B = g_ztxt_h;
    int tid = threadIdx.x;
    int lane = tid & 31, warp = tid >> 5;
    int wm = warp >> 1, wn = warp & 1;  // 4x2 warp grid; warp tile 32x64
    size_t m0 = (size_t)blockIdx.y * BM;
    size_t n0 = (size_t)blockIdx.x * BN;

    float acc[2][8][4];
#pragma unroll
    for (int i = 0; i < 2; i++)
#pragma unroll
        for (int j = 0; j < 8; j++)
#pragma unroll
            for (int r = 0; r < 4; r++) acc[i][j][r] = 0.f;

    // buffer index table for s % 3 without division
    auto buf_of = [](int s) { return s - (s / NBUF) * NBUF; };

    auto load_stage = [&](int s) {
        char* st = smem + buf_of(s) * STAGE_BYTES;
        int kof = s * BKH;
#pragma unroll
        for (int i = 0; i < 4; i++) {
            int e = tid + i * 256;
            int r = e >> 3, c = e & 7;
            cp16(st + r * LDHB + c * 16, A + (m0 + r) * DIM + kof + c * 8);
        }
        char* stb = st + AREG;
#pragma unroll
        for (int i = 0; i < 4; i++) {
            int e = tid + i * 256;
            int r = e >> 3, c = e & 7;
            cp16(stb + r * LDHB + c * 16, B + (n0 + r) * DIM + kof + c * 8);
        }
        asm volatile("cp.async.commit_group;\n" ::: "memory");
    };

    load_stage(0);
    load_stage(1);

    int lrow = lane & 7;
    int aRow = ((lane >> 3) & 1) * 8 + lrow;
    int aColB = (lane >> 4) * 16;
    int bRow = (lane >> 4) * 8 + lrow;
    int bColB = ((lane >> 3) & 1) * 16;

    for (int kt = 0; kt < NSTG; kt++) {
        if (kt < NSTG - 1) asm volatile("cp.async.wait_group 1;" ::: "memory");
        else               asm volatile("cp.async.wait_group 0;" ::: "memory");
        __syncthreads();  // SINGLE barrier per stage

        // prefetch kt+2 into buffer (kt+2)%3 — distinct from compute (kt%3)
        // and in-flight (kt+1)%3; prior-stage readers passed the barrier.
        if (kt + 2 < NSTG) load_stage(kt + 2);

        uint32_t base = sb + buf_of(kt) * STAGE_BYTES;
        uint32_t baseA = base + (wm * 32 + aRow) * LDHB + aColB;
        uint32_t baseB = base + AREG + (wn * 64 + bRow) * LDHB + bColB;
#pragma unroll
        for (int ks = 0; ks < BKH / 16; ks++) {
            uint32_t kb = ks * 32;
            uint32_t af[2][4], bf[8][2];
#pragma unroll
            for (int mi = 0; mi < 2; mi++)
                LDSM4(af[mi][0], af[mi][1], af[mi][2], af[mi][3],
                      baseA + mi * 16 * LDHB + kb);
#pragma unroll
            for (int p = 0; p < 4; p++)
                LDSM4(bf[2 * p][0], bf[2 * p][1], bf[2 * p + 1][0], bf[2 * p + 1][1],
                      baseB + p * 16 * LDHB + kb);
#pragma unroll
            for (int mi = 0; mi < 2; mi++)
#pragma unroll
                for (int ni = 0; ni < 8; ni++) mmaf16(acc[mi][ni], af[mi], bf[ni]);
        }
    }

    float t = expf(logt[0]);
    float bb = bias[0];
#pragma unroll
    for (int mi = 0; mi < 2; mi++)
#pragma unroll
        for (int ni = 0; ni < 8; ni++) {
            size_t row = m0 + wm * 32 + mi * 16 + (lane >> 2);
            size_t col = n0 + wn * 64 + ni * 8 + (size_t)(lane & 3) * 2;
            float* p0 = C + row * N_TXT + col;          // scalar: d_out 4B-aligned
            float* p1 = C + (row + 8) * N_TXT + col;
            p0[0] = fmaf(acc[mi][ni][0], t, bb);
            p0[1] = fmaf(acc[mi][ni][1], t, bb);
            p1[0] = fmaf(acc[mi][ni][2], t, bb);
            p1[1] = fmaf(acc[mi][ni][3], t, bb);
        }
}

// ---------------- fused gather + row loss ----------------------------------------
__global__ void gather_fl_kernel(const float* __restrict__ AP, float* __restrict__ FL,
                                 const float* __restrict__ bias) {
    int j = blockIdx.x;
    int sel = g_sel[j];
    bool valid = sel < S_IMG;
    const float* src = AP + (size_t)(valid ? sel : 0) * N_TXT;
    float bb = bias[0];
    float* dst = FL + (size_t)j * N_TXT;
    float s = 0.f;
    for (int c = threadIdx.x; c < N_TXT; c += blockDim.x) {
        float x = valid ? src[c] : bb;
        dst[c] = x;
        float z = (c == j) ? -x : x;  // softplus(-(label*x)), label = 2*eye-1
        s += fmaxf(z, 0.f) + __logf(1.f + __expf(-fabsf(z)));
    }
#pragma unroll
    for (int o = 16; o; o >>= 1) s += __shfl_down_sync(0xffffffffu, s, o);
    __shared__ float sm[8];
    if ((threadIdx.x & 31) == 0) sm[threadIdx.x >> 5] = s;
    __syncthreads();
    if (threadIdx.x == 0) {
        float tot = 0.f;
#pragma unroll
        for (int w = 0; w < 8; w++) tot += sm[w];
        g_rowsum[j] = tot;
    }
}

__global__ void finalize_kernel(float* __restrict__ out) {
    int tid = threadIdx.x;
    double s = 0.0;
    for (int i = tid; i < N_TXT; i += 256) s += (double)g_rowsum[i];
#pragma unroll
    for (int o = 16; o; o >>= 1) s += __shfl_down_sync(0xffffffffu, s, o);
    __shared__ double sm[8];
    if ((tid & 31) == 0) sm[tid >> 5] = s;
    __syncthreads();
    if (tid == 0) {
        double tot = 0.0;
#pragma unroll
        for (int w = 0; w < 8; w++) tot += sm[w];
        out[0] = (float)(tot / (double)N_TXT);
    }
}

// ---------------- launch ---------------------------------------------------------
extern "C" void kernel_launch(void* const* d_in, const int* in_sizes, int n_in,
                              void* d_out, int out_size) {
    const float* img  = (const float*)d_in[0];
    const float* txt  = (const float*)d_in[1];
    const int*   key  = (const int*)d_in[2];
    const float* logt = (const float*)d_in[3];
    const float* bias = (const float*)d_in[4];

    float* out      = (float*)d_out;
    float* out_loss = out;                                   // [1]
    float* out_sel  = out + 1;                               // [4096]
    float* out_zimg = out_sel + N_TXT;                       // [16384*512]
    float* out_ztxt = out_zimg + (size_t)S_IMG * DIM;        // [4096*512]
    float* out_ap   = out_ztxt + (size_t)N_TXT * DIM;        // [16384*4096]
    float* out_fl   = out_ap + (size_t)S_IMG * N_TXT;        // [4096*4096]

    cudaFuncSetAttribute(gemm_kernel, cudaFuncAttributeMaxDynamicSharedMemorySize, GSMEM_BYTES);

    // single launch: normalize all rows (txt rows also init segmin/sel)
    norm_all_kernel<<<S_IMG + N_TXT, 128>>>(img, txt, out_zimg, out_ztxt);

    // fork: cheap exact-fp32 selection chain on side stream (hides under GEMM1)
    cudaEventRecord(g_fork, 0);
    cudaStreamWaitEvent(g_side, g_fork, 0);
    tp_kernel<<<S_IMG / 8, 256, 0, g_side>>>(out_zimg, out_ztxt, key, logt, bias);
    pick_kernel<<<S_IMG / 256, 256, 0, g_side>>>(key);
    sel_kernel<<<(N_TXT + 255) / 256, 256, 0, g_side>>>(out_sel);
    cudaEventRecord(g_join, g_side);

    // main stream: big GEMM (all_pairs_logits [16384, 4096])
    gemm_kernel<<<dim3(N_TXT / BN, S_IMG / BM), 256, GSMEM_BYTES>>>(out_ap, logt, bias);

    // join, then final_logits = row-gather of all_pairs (fused with row loss)
    cudaStreamWaitEvent(0, g_join, 0);
    gather_fl_kernel<<<N_TXT, 256>>>(out_ap, out_fl, bias);
    finalize_kernel<<<1, 256>>>(out_loss);
}

// round 13
// speedup vs baseline: 1.1012x; 1.0445x over previous
#include <cuda_runtime.h>
#include <cuda_fp16.h>
#include <cstdint>
#include <math.h>

#define S_IMG 16384
#define N_TXT 4096
#define DIM   512

// ---------------- scratch (static device globals; no allocations) ----------------
__device__ __half g_zimg_h[(size_t)S_IMG * DIM];  // fp16 zimg
__device__ __half g_ztxt_h[(size_t)N_TXT * DIM];  // fp16 ztxt
__device__ float  g_loss[S_IMG];
__device__ int    g_segmin[N_TXT];
__device__ int    g_sel[N_TXT];
__device__ float  g_rowsum[N_TXT];

// ---------------- streams/events: created at program load; reused every call ----
static cudaStream_t g_side;
static cudaEvent_t  g_fork, g_join;
struct _StreamInit {
    _StreamInit() {
        cudaStreamCreateWithFlags(&g_side, cudaStreamNonBlocking);
        cudaEventCreateWithFlags(&g_fork, cudaEventDisableTiming);
        cudaEventCreateWithFlags(&g_join, cudaEventDisableTiming);
    }
};
static _StreamInit g_si;

// ---------------- L2 normalize (img+txt in ONE launch): exact fp32 to d_out
// (scalar stores; d_out only 4B-aligned), fp16 copy to scratch; txt rows also
// init segmin/sel ----------------------------------------------------------------
__global__ void norm_all_kernel(const float* __restrict__ img, const float* __restrict__ txt,
                                float* __restrict__ dimg, float* __restrict__ dtxt) {
    int row = blockIdx.x;
    int tid = threadIdx.x;  // 128 threads, each one float4 (512 elems)
    bool istxt = row >= S_IMG;
    const float* src;
    float* dst;
    __half* dst_h;
    if (istxt) {
        row -= S_IMG;
        src = txt; dst = dtxt; dst_h = g_ztxt_h;
        if (tid == 0) { g_segmin[row] = 0x7F800000; g_sel[row] = S_IMG; }
    } else {
        src = img; dst = dimg; dst_h = g_zimg_h;
    }
    float4 v = reinterpret_cast<const float4*>(src + (size_t)row * DIM)[tid];
    float p = v.x * v.x + v.y * v.y + v.z * v.z + v.w * v.w;
#pragma unroll
    for (int o = 16; o; o >>= 1) p += __shfl_down_sync(0xffffffffu, p, o);
    __shared__ float ws[4];
    __shared__ float nshared;
    if ((tid & 31) == 0) ws[tid >> 5] = p;
    __syncthreads();
    if (tid == 0) nshared = sqrtf(ws[0] + ws[1] + ws[2] + ws[3]) + 1e-12f;
    __syncthreads();
    float n = nshared;
    float4 o;
    o.x = v.x / n; o.y = v.y / n; o.z = v.z / n; o.w = v.w / n;
    float* drow = dst + (size_t)row * DIM + tid * 4;
    drow[0] = o.x; drow[1] = o.y; drow[2] = o.z; drow[3] = o.w;
    __half2* hp = reinterpret_cast<__half2*>(dst_h + (size_t)row * DIM);
    hp[tid * 2]     = __floats2half2_rn(o.x, o.y);
    hp[tid * 2 + 1] = __floats2half2_rn(o.z, o.w);
}

// ---------------- exact fp32 true-positive logits + segment-min -----------------
__global__ void tp_kernel(const float* __restrict__ zimg, const float* __restrict__ ztxt,
                          const int* __restrict__ key, const float* __restrict__ logt,
                          const float* __restrict__ bias) {
    int gw = (blockIdx.x * blockDim.x + threadIdx.x) >> 5;
    int lane = threadIdx.x & 31;
    if (gw >= S_IMG) return;
    int k = key[gw];
    const float* a = zimg + (size_t)gw * DIM;
    const float* b = ztxt + (size_t)k * DIM;
    float s = 0.f;
#pragma unroll
    for (int j = 0; j < DIM / 32; j++) s = fmaf(a[lane + j * 32], b[lane + j * 32], s);
#pragma unroll
    for (int o = 16; o; o >>= 1) s += __shfl_down_sync(0xffffffffu, s, o);
    if (lane == 0) {
        float t = expf(logt[0]);
        float tpl = fmaf(s, t, bias[0]);
        float x = -tpl;
        float loss = fmaxf(x, 0.f) + log1pf(expf(-fabsf(x)));
        g_loss[gw] = loss;
        atomicMin(&g_segmin[k], __float_as_int(loss));  // loss >= 0 -> bit order ok
    }
}

__global__ void pick_kernel(const int* __restrict__ key) {
    int i = blockIdx.x * blockDim.x + threadIdx.x;
    if (i < S_IMG) {
        int k = key[i];
        if (__float_as_int(g_loss[i]) == g_segmin[k]) atomicMin(&g_sel[k], i);
    }
}

__global__ void sel_kernel(float* __restrict__ out_idx) {
    int j = blockIdx.x * blockDim.x + threadIdx.x;
    if (j < N_TXT) {
        int sel = g_sel[j];
        out_idx[j] = (sel < S_IMG) ? (float)sel : -1.0f;
    }
}

// ---------------- fp16 mma.sync GEMM (R12 + register-level frag pipelining) ------
#define BM 128
#define BN 128
#define BKH 64                                  // fp16 k per stage
#define NSTG (DIM / BKH)                        // 8
#define NBUF 3
#define LDHB 144                                // bytes per smem row (64 fp16 + 8 pad)
#define AREG (BM * LDHB)                        // 18432
#define STAGE_BYTES (2 * AREG)                  // 36864 (A + B)
#define GSMEM_BYTES (NBUF * STAGE_BYTES)        // 110592; 2 CTAs = 216KB <= 228KB

__device__ __forceinline__ uint32_t smem_u32(const void* p) {
    uint32_t a;
    asm("{ .reg .u64 t; cvta.to.shared.u64 t, %1; cvt.u32.u64 %0, t; }" : "=r"(a) : "l"(p));
    return a;
}
__device__ __forceinline__ void cp16(void* s, const void* g) {
    uint32_t sa = smem_u32(s);
    asm volatile("cp.async.cg.shared.global [%0], [%1], 16;\n" ::"r"(sa), "l"(g) : "memory");
}
#define LDSM4(r0, r1, r2, r3, addr)                                            \
    asm volatile("ldmatrix.sync.aligned.m8n8.x4.shared.b16 {%0,%1,%2,%3}, [%4];" \
                 : "=r"(r0), "=r"(r1), "=r"(r2), "=r"(r3) : "r"(addr))

__device__ __forceinline__ void mmaf16(float* d, const uint32_t* a, const uint32_t* b) {
    asm volatile(
        "mma.sync.aligned.m16n8k16.row.col.f32.f16.f16.f32 "
        "{%0,%1,%2,%3}, {%4,%5,%6,%7}, {%8,%9}, {%0,%1,%2,%3};\n"
        : "+f"(d[0]), "+f"(d[1]), "+f"(d[2]), "+f"(d[3])
        : "r"(a[0]), "r"(a[1]), "r"(a[2]), "r"(a[3]), "r"(b[0]), "r"(b[1]));
}

__global__ __launch_bounds__(256, 2) void gemm_kernel(float* __restrict__ C,
                                                      const float* __restrict__ logt,
                                                      const float* __restrict__ bias) {
    extern __shared__ __align__(128) char smem[];
    uint32_t sb = smem_u32(smem);
    const __half* A = g_zimg_h;
    const __half* B = g_ztxt_h;
    int tid = threadIdx.x;
    int lane = tid & 31, warp = tid >> 5;
    int wm = warp >> 1, wn = warp & 1;  // 4x2 warp grid; warp tile 32x64
    size_t m0 = (size_t)blockIdx.y * BM;
    size_t n0 = (size_t)blockIdx.x * BN;

    float acc[2][8][4];
#pragma unroll
    for (int i = 0; i < 2; i++)
#pragma unroll
        for (int j = 0; j < 8; j++)
#pragma unroll
            for (int r = 0; r < 4; r++) acc[i][j][r] = 0.f;

    auto load_stage = [&](int s, int buf) {
        char* st = smem + buf * STAGE_BYTES;
        int kof = s * BKH;
#pragma unroll
        for (int i = 0; i < 4; i++) {
            int e = tid + i * 256;
            int r = e >> 3, c = e & 7;
            cp16(st + r * LDHB + c * 16, A + (m0 + r) * DIM + kof + c * 8);
        }
        char* stb = st + AREG;
#pragma unroll
        for (int i = 0; i < 4; i++) {
            int e = tid + i * 256;
            int r = e >> 3, c = e & 7;
            cp16(stb + r * LDHB + c * 16, B + (n0 + r) * DIM + kof + c * 8);
        }
        asm volatile("cp.async.commit_group;\n" ::: "memory");
    };

    load_stage(0, 0);
    load_stage(1, 1);

    int lrow = lane & 7;
    int aRow = ((lane >> 3) & 1) * 8 + lrow;
    int aColB = (lane >> 4) * 16;
    int bRow = (lane >> 4) * 8 + lrow;
    int bColB = ((lane >> 3) & 1) * 16;

    // register fragment double buffers
    uint32_t af[2][2][4], bf[2][8][2];

#pragma unroll
    for (int kt = 0; kt < NSTG; kt++) {
        const int buf = kt % NBUF;                   // constant after unroll
        if (kt < NSTG - 1) asm volatile("cp.async.wait_group 1;" ::: "memory");
        else               asm volatile("cp.async.wait_group 0;" ::: "memory");
        __syncthreads();  // single barrier per stage

        if (kt + 2 < NSTG) load_stage(kt + 2, (kt + 2) % NBUF);

        uint32_t base = sb + buf * STAGE_BYTES;
        uint32_t baseA = base + (wm * 32 + aRow) * LDHB + aColB;
        uint32_t baseB = base + AREG + (wn * 64 + bRow) * LDHB + bColB;

        // prologue fragment load (ks=0 -> pb 0)
#pragma unroll
        for (int mi = 0; mi < 2; mi++)
            LDSM4(af[0][mi][0], af[0][mi][1], af[0][mi][2], af[0][mi][3],
                  baseA + mi * 16 * LDHB);
#pragma unroll
        for (int p = 0; p < 4; p++)
            LDSM4(bf[0][2 * p][0], bf[0][2 * p][1], bf[0][2 * p + 1][0], bf[0][2 * p + 1][1],
                  baseB + p * 16 * LDHB);

#pragma unroll
        for (int ks = 0; ks < BKH / 16; ks++) {
            int cur = ks & 1, nxt = cur ^ 1;
            if (ks < BKH / 16 - 1) {               // prefetch fragments for ks+1
                uint32_t kb = (ks + 1) * 32;
#pragma unroll
                for (int mi = 0; mi < 2; mi++)
                    LDSM4(af[nxt][mi][0], af[nxt][mi][1], af[nxt][mi][2], af[nxt][mi][3],
                          baseA + mi * 16 * LDHB + kb);
#pragma unroll
                for (int p = 0; p < 4; p++)
                    LDSM4(bf[nxt][2 * p][0], bf[nxt][2 * p][1],
                          bf[nxt][2 * p + 1][0], bf[nxt][2 * p + 1][1],
                          baseB + p * 16 * LDHB + kb);
            }
#pragma unroll
            for (int mi = 0; mi < 2; mi++)
#pragma unroll
                for (int ni = 0; ni < 8; ni++) mmaf16(acc[mi][ni], af[cur][mi], bf[cur][ni]);
        }
    }

    float t = expf(logt[0]);
    float bb = bias[0];
#pragma unroll
    for (int mi = 0; mi < 2; mi++)
#pragma unroll
        for (int ni = 0; ni < 8; ni++) {
            size_t row = m0 + wm * 32 + mi * 16 + (lane >> 2);
            size_t col = n0 + wn * 64 + ni * 8 + (size_t)(lane & 3) * 2;
            float* p0 = C + row * N_TXT + col;          // scalar: d_out 4B-aligned
            float* p1 = C + (row + 8) * N_TXT + col;
            p0[0] = fmaf(acc[mi][ni][0], t, bb);
            p0[1] = fmaf(acc[mi][ni][1], t, bb);
            p1[0] = fmaf(acc[mi][ni][2], t, bb);
            p1[1] = fmaf(acc[mi][ni][3], t, bb);
        }
}

// ---------------- fused gather + row loss ----------------------------------------
__global__ void gather_fl_kernel(const float* __restrict__ AP, float* __restrict__ FL,
                                 const float* __restrict__ bias) {
    int j = blockIdx.x;
    int sel = g_sel[j];
    bool valid = sel < S_IMG;
    const float* src = AP + (size_t)(valid ? sel : 0) * N_TXT;
    float bb = bias[0];
    float* dst = FL + (size_t)j * N_TXT;
    float s = 0.f;
    for (int c = threadIdx.x; c < N_TXT; c += blockDim.x) {
        float x = valid ? src[c] : bb;
        dst[c] = x;
        float z = (c == j) ? -x : x;  // softplus(-(label*x)), label = 2*eye-1
        s += fmaxf(z, 0.f) + __logf(1.f + __expf(-fabsf(z)));
    }
#pragma unroll
    for (int o = 16; o; o >>= 1) s += __shfl_down_sync(0xffffffffu, s, o);
    __shared__ float sm[8];
    if ((threadIdx.x & 31) == 0) sm[threadIdx.x >> 5] = s;
    __syncthreads();
    if (threadIdx.x == 0) {
        float tot = 0.f;
#pragma unroll
        for (int w = 0; w < 8; w++) tot += sm[w];
        g_rowsum[j] = tot;
    }
}

__global__ void finalize_kernel(float* __restrict__ out) {
    int tid = threadIdx.x;
    double s = 0.0;
    for (int i = tid; i < N_TXT; i += 256) s += (double)g_rowsum[i];
#pragma unroll
    for (int o = 16; o; o >>= 1) s += __shfl_down_sync(0xffffffffu, s, o);
    __shared__ double sm[8];
    if ((tid & 31) == 0) sm[tid >> 5] = s;
    __syncthreads();
    if (tid == 0) {
        double tot = 0.0;
#pragma unroll
        for (int w = 0; w < 8; w++) tot += sm[w];
        out[0] = (float)(tot / (double)N_TXT);
    }
}

// ---------------- launch ---------------------------------------------------------
extern "C" void kernel_launch(void* const* d_in, const int* in_sizes, int n_in,
                              void* d_out, int out_size) {
    const float* img  = (const float*)d_in[0];
    const float* txt  = (const float*)d_in[1];
    const int*   key  = (const int*)d_in[2];
    const float* logt = (const float*)d_in[3];
    const float* bias = (const float*)d_in[4];

    float* out      = (float*)d_out;
    float* out_loss = out;                                   // [1]
    float* out_sel  = out + 1;                               // [4096]
    float* out_zimg = out_sel + N_TXT;                       // [16384*512]
    float* out_ztxt = out_zimg + (size_t)S_IMG * DIM;        // [4096*512]
    float* out_ap   = out_ztxt + (size_t)N_TXT * DIM;        // [16384*4096]
    float* out_fl   = out_ap + (size_t)S_IMG * N_TXT;        // [4096*4096]

    cudaFuncSetAttribute(gemm_kernel, cudaFuncAttributeMaxDynamicSharedMemorySize, GSMEM_BYTES);

    // single launch: normalize all rows (txt rows also init segmin/sel)
    norm_all_kernel<<<S_IMG + N_TXT, 128>>>(img, txt, out_zimg, out_ztxt);

    // fork: cheap exact-fp32 selection chain on side stream (hides under GEMM1)
    cudaEventRecord(g_fork, 0);
    cudaStreamWaitEvent(g_side, g_fork, 0);
    tp_kernel<<<S_IMG / 8, 256, 0, g_side>>>(out_zimg, out_ztxt, key, logt, bias);
    pick_kernel<<<S_IMG / 256, 256, 0, g_side>>>(key);
    sel_kernel<<<(N_TXT + 255) / 256, 256, 0, g_side>>>(out_sel);
    cudaEventRecord(g_join, g_side);

    // main stream: big GEMM (all_pairs_logits [16384, 4096])
    gemm_kernel<<<dim3(N_TXT / BN, S_IMG / BM), 256, GSMEM_BYTES>>>(out_ap, logt, bias);

    // join, then final_logits = row-gather of all_pairs (fused with row loss)
    cudaStreamWaitEvent(0, g_join, 0);
    gather_fl_kernel<<<N_TXT, 256>>>(out_ap, out_fl, bias);
    finalize_kernel<<<1, 256>>>(out_loss);
}

// round 14
// speedup vs baseline: 1.1397x; 1.0350x over previous
#include <cuda_runtime.h>
#include <cuda_fp16.h>
#include <cstdint>
#include <math.h>

#define S_IMG 16384
#define N_TXT 4096
#define DIM   512

// ---------------- scratch (static device globals; no allocations) ----------------
__device__ __half g_zimg_h[(size_t)S_IMG * DIM];  // fp16 zimg
__device__ __half g_ztxt_h[(size_t)N_TXT * DIM];  // fp16 ztxt
__device__ float  g_loss[S_IMG];
__device__ int    g_segmin[N_TXT];
__device__ int    g_sel[N_TXT];
__device__ float  g_rowsum[N_TXT];

// ---------------- streams/events: created at program load; reused every call ----
static cudaStream_t g_side;
static cudaEvent_t  g_fork, g_join;
struct _StreamInit {
    _StreamInit() {
        cudaStreamCreateWithFlags(&g_side, cudaStreamNonBlocking);
        cudaEventCreateWithFlags(&g_fork, cudaEventDisableTiming);
        cudaEventCreateWithFlags(&g_join, cudaEventDisableTiming);
    }
};
static _StreamInit g_si;

// ---------------- L2 normalize (img+txt in ONE launch): exact fp32 to d_out
// (scalar stores; d_out only 4B-aligned), fp16 copy to scratch; txt rows also
// init segmin/sel/rowsum ----------------------------------------------------------
__global__ void norm_all_kernel(const float* __restrict__ img, const float* __restrict__ txt,
                                float* __restrict__ dimg, float* __restrict__ dtxt) {
    int row = blockIdx.x;
    int tid = threadIdx.x;  // 128 threads, each one float4 (512 elems)
    bool istxt = row >= S_IMG;
    const float* src;
    float* dst;
    __half* dst_h;
    if (istxt) {
        row -= S_IMG;
        src = txt; dst = dtxt; dst_h = g_ztxt_h;
        if (tid == 0) { g_segmin[row] = 0x7F800000; g_sel[row] = S_IMG; g_rowsum[row] = 0.f; }
    } else {
        src = img; dst = dimg; dst_h = g_zimg_h;
    }
    float4 v = reinterpret_cast<const float4*>(src + (size_t)row * DIM)[tid];
    float p = v.x * v.x + v.y * v.y + v.z * v.z + v.w * v.w;
#pragma unroll
    for (int o = 16; o; o >>= 1) p += __shfl_down_sync(0xffffffffu, p, o);
    __shared__ float ws[4];
    __shared__ float nshared;
    if ((tid & 31) == 0) ws[tid >> 5] = p;
    __syncthreads();
    if (tid == 0) nshared = sqrtf(ws[0] + ws[1] + ws[2] + ws[3]) + 1e-12f;
    __syncthreads();
    float n = nshared;
    float4 o;
    o.x = v.x / n; o.y = v.y / n; o.z = v.z / n; o.w = v.w / n;
    float* drow = dst + (size_t)row * DIM + tid * 4;
    drow[0] = o.x; drow[1] = o.y; drow[2] = o.z; drow[3] = o.w;
    __half2* hp = reinterpret_cast<__half2*>(dst_h + (size_t)row * DIM);
    hp[tid * 2]     = __floats2half2_rn(o.x, o.y);
    hp[tid * 2 + 1] = __floats2half2_rn(o.z, o.w);
}

// ---------------- exact fp32 true-positive logits + segment-min -----------------
__global__ void tp_kernel(const float* __restrict__ zimg, const float* __restrict__ ztxt,
                          const int* __restrict__ key, const float* __restrict__ logt,
                          const float* __restrict__ bias) {
    int gw = (blockIdx.x * blockDim.x + threadIdx.x) >> 5;
    int lane = threadIdx.x & 31;
    if (gw >= S_IMG) return;
    int k = key[gw];
    const float* a = zimg + (size_t)gw * DIM;
    const float* b = ztxt + (size_t)k * DIM;
    float s = 0.f;
#pragma unroll
    for (int j = 0; j < DIM / 32; j++) s = fmaf(a[lane + j * 32], b[lane + j * 32], s);
#pragma unroll
    for (int o = 16; o; o >>= 1) s += __shfl_down_sync(0xffffffffu, s, o);
    if (lane == 0) {
        float t = expf(logt[0]);
        float tpl = fmaf(s, t, bias[0]);
        float x = -tpl;
        float loss = fmaxf(x, 0.f) + log1pf(expf(-fabsf(x)));
        g_loss[gw] = loss;
        atomicMin(&g_segmin[k], __float_as_int(loss));  // loss >= 0 -> bit order ok
    }
}

__global__ void pick_kernel(const int* __restrict__ key) {
    int i = blockIdx.x * blockDim.x + threadIdx.x;
    if (i < S_IMG) {
        int k = key[i];
        if (__float_as_int(g_loss[i]) == g_segmin[k]) atomicMin(&g_sel[k], i);
    }
}

__global__ void sel_kernel(float* __restrict__ out_idx) {
    int j = blockIdx.x * blockDim.x + threadIdx.x;
    if (j < N_TXT) {
        int sel = g_sel[j];
        out_idx[j] = (sel < S_IMG) ? (float)sel : -1.0f;
    }
}

// fill FL rows for invalid (empty-segment) texts with bias; set their rowsum ------
__global__ void fl_fill_kernel(float* __restrict__ FL, const float* __restrict__ bias) {
    int j = blockIdx.x;
    if (g_sel[j] < S_IMG) return;
    float bb = bias[0];
    float* dst = FL + (size_t)j * N_TXT;
    for (int c = threadIdx.x; c < N_TXT; c += blockDim.x) dst[c] = bb;
    if (threadIdx.x == 0) {
        // diag label +1 -> softplus(-bb); 4095 off-diag label -1 -> softplus(bb)
        float sp_n = fmaxf(-bb, 0.f) + log1pf(expf(-fabsf(bb)));
        float sp_p = fmaxf(bb, 0.f) + log1pf(expf(-fabsf(bb)));
        g_rowsum[j] = sp_n + 4095.0f * sp_p;
    }
}

// ---------------- fp16 mma.sync GEMM (R13 core + fused FL scatter epilogue) ------
#define BM 128
#define BN 128
#define BKH 64                                  // fp16 k per stage
#define NSTG (DIM / BKH)                        // 8
#define NBUF 3
#define LDHB 144                                // bytes per smem row (64 fp16 + 8 pad)
#define AREG (BM * LDHB)                        // 18432
#define STAGE_BYTES (2 * AREG)                  // 36864 (A + B)
#define GSMEM_BYTES (NBUF * STAGE_BYTES)        // 110592; 2 CTAs = 216KB <= 228KB

__device__ __forceinline__ uint32_t smem_u32(const void* p) {
    uint32_t a;
    asm("{ .reg .u64 t; cvta.to.shared.u64 t, %1; cvt.u32.u64 %0, t; }" : "=r"(a) : "l"(p));
    return a;
}
__device__ __forceinline__ void cp16(void* s, const void* g) {
    uint32_t sa = smem_u32(s);
    asm volatile("cp.async.cg.shared.global [%0], [%1], 16;\n" ::"r"(sa), "l"(g) : "memory");
}
#define LDSM4(r0, r1, r2, r3, addr)                                            \
    asm volatile("ldmatrix.sync.aligned.m8n8.x4.shared.b16 {%0,%1,%2,%3}, [%4];" \
                 : "=r"(r0), "=r"(r1), "=r"(r2), "=r"(r3) : "r"(addr))

__device__ __forceinline__ void mmaf16(float* d, const uint32_t* a, const uint32_t* b) {
    asm volatile(
        "mma.sync.aligned.m16n8k16.row.col.f32.f16.f16.f32 "
        "{%0,%1,%2,%3}, {%4,%5,%6,%7}, {%8,%9}, {%0,%1,%2,%3};\n"
        : "+f"(d[0]), "+f"(d[1]), "+f"(d[2]), "+f"(d[3])
        : "r"(a[0]), "r"(a[1]), "r"(a[2]), "r"(a[3]), "r"(b[0]), "r"(b[1]));
}

__global__ __launch_bounds__(256, 2) void gemm_kernel(float* __restrict__ C,
                                                      float* __restrict__ FL,
                                                      const int* __restrict__ key,
                                                      const float* __restrict__ logt,
                                                      const float* __restrict__ bias) {
    extern __shared__ __align__(128) char smem[];
    uint32_t sb = smem_u32(smem);
    const __half* A = g_zimg_h;
    const __half* B = g_ztxt_h;
    int tid = threadIdx.x;
    int lane = tid & 31, warp = tid >> 5;
    int wm = warp >> 1, wn = warp & 1;  // 4x2 warp grid; warp tile 32x64
    size_t m0 = (size_t)blockIdx.y * BM;
    size_t n0 = (size_t)blockIdx.x * BN;

    float acc[2][8][4];
#pragma unroll
    for (int i = 0; i < 2; i++)
#pragma unroll
        for (int j = 0; j < 8; j++)
#pragma unroll
            for (int r = 0; r < 4; r++) acc[i][j][r] = 0.f;

    auto load_stage = [&](int s, int buf) {
        char* st = smem + buf * STAGE_BYTES;
        int kof = s * BKH;
#pragma unroll
        for (int i = 0; i < 4; i++) {
            int e = tid + i * 256;
            int r = e >> 3, c = e & 7;
            cp16(st + r * LDHB + c * 16, A + (m0 + r) * DIM + kof + c * 8);
        }
        char* stb = st + AREG;
#pragma unroll
        for (int i = 0; i < 4; i++) {
            int e = tid + i * 256;
            int r = e >> 3, c = e & 7;
            cp16(stb + r * LDHB + c * 16, B + (n0 + r) * DIM + kof + c * 8);
        }
        asm volatile("cp.async.commit_group;\n" ::: "memory");
    };

    load_stage(0, 0);
    load_stage(1, 1);

    int lrow = lane & 7;
    int aRow = ((lane >> 3) & 1) * 8 + lrow;
    int aColB = (lane >> 4) * 16;
    int bRow = (lane >> 4) * 8 + lrow;
    int bColB = ((lane >> 3) & 1) * 16;

    uint32_t af[2][2][4], bf[2][8][2];  // register fragment double buffers

#pragma unroll
    for (int kt = 0; kt < NSTG; kt++) {
        const int buf = kt % NBUF;
        if (kt < NSTG - 1) asm volatile("cp.async.wait_group 1;" ::: "memory");
        else               asm volatile("cp.async.wait_group 0;" ::: "memory");
        __syncthreads();  // single barrier per stage

        if (kt + 2 < NSTG) load_stage(kt + 2, (kt + 2) % NBUF);

        uint32_t base = sb + buf * STAGE_BYTES;
        uint32_t baseA = base + (wm * 32 + aRow) * LDHB + aColB;
        uint32_t baseB = base + AREG + (wn * 64 + bRow) * LDHB + bColB;

#pragma unroll
        for (int mi = 0; mi < 2; mi++)
            LDSM4(af[0][mi][0], af[0][mi][1], af[0][mi][2], af[0][mi][3],
                  baseA + mi * 16 * LDHB);
#pragma unroll
        for (int p = 0; p < 4; p++)
            LDSM4(bf[0][2 * p][0], bf[0][2 * p][1], bf[0][2 * p + 1][0], bf[0][2 * p + 1][1],
                  baseB + p * 16 * LDHB);

#pragma unroll
        for (int ks = 0; ks < BKH / 16; ks++) {
            int cur = ks & 1, nxt = cur ^ 1;
            if (ks < BKH / 16 - 1) {
                uint32_t kb = (ks + 1) * 32;
#pragma unroll
                for (int mi = 0; mi < 2; mi++)
                    LDSM4(af[nxt][mi][0], af[nxt][mi][1], af[nxt][mi][2], af[nxt][mi][3],
                          baseA + mi * 16 * LDHB + kb);
#pragma unroll
                for (int p = 0; p < 4; p++)
                    LDSM4(bf[nxt][2 * p][0], bf[nxt][2 * p][1],
                          bf[nxt][2 * p + 1][0], bf[nxt][2 * p + 1][1],
                          baseB + p * 16 * LDHB + kb);
            }
#pragma unroll
            for (int mi = 0; mi < 2; mi++)
#pragma unroll
                for (int ni = 0; ni < 8; ni++) mmaf16(acc[mi][ni], af[cur][mi], bf[cur][ni]);
        }
    }

    // epilogue: store AP; for selected rows (g_sel[key[r]] == r, sel injective)
    // scatter into FL[j,:] and accumulate softplus partial row-sums.
    float t = expf(logt[0]);
    float bb = bias[0];
#pragma unroll
    for (int mi = 0; mi < 2; mi++)
#pragma unroll
        for (int half = 0; half < 2; half++) {
            size_t row = m0 + wm * 32 + mi * 16 + (lane >> 2) + half * 8;
            int j = key[row];
            bool selrow = (g_sel[j] == (int)row);
            float lsum = 0.f;
#pragma unroll
            for (int ni = 0; ni < 8; ni++) {
                size_t col = n0 + wn * 64 + ni * 8 + (size_t)(lane & 3) * 2;
                float v0 = fmaf(acc[mi][ni][half * 2 + 0], t, bb);
                float v1 = fmaf(acc[mi][ni][half * 2 + 1], t, bb);
                float* p = C + row * N_TXT + col;   // scalar: d_out 4B-aligned
                p[0] = v0;
                p[1] = v1;
                if (selrow) {
                    float* q = FL + (size_t)j * N_TXT + col;
                    q[0] = v0;
                    q[1] = v1;
                    float z0 = ((int)col == j) ? -v0 : v0;
                    float z1 = ((int)col + 1 == j) ? -v1 : v1;
                    lsum += fmaxf(z0, 0.f) + __logf(1.f + __expf(-fabsf(z0)));
                    lsum += fmaxf(z1, 0.f) + __logf(1.f + __expf(-fabsf(z1)));
                }
            }
            if (selrow) atomicAdd(&g_rowsum[j], lsum);
        }
}

__global__ void finalize_kernel(float* __restrict__ out) {
    int tid = threadIdx.x;
    double s = 0.0;
    for (int i = tid; i < N_TXT; i += 256) s += (double)g_rowsum[i];
#pragma unroll
    for (int o = 16; o; o >>= 1) s += __shfl_down_sync(0xffffffffu, s, o);
    __shared__ double sm[8];
    if ((tid & 31) == 0) sm[tid >> 5] = s;
    __syncthreads();
    if (tid == 0) {
        double tot = 0.0;
#pragma unroll
        for (int w = 0; w < 8; w++) tot += sm[w];
        out[0] = (float)(tot / (double)N_TXT);
    }
}

// ---------------- launch ---------------------------------------------------------
extern "C" void kernel_launch(void* const* d_in, const int* in_sizes, int n_in,
                              void* d_out, int out_size) {
    const float* img  = (const float*)d_in[0];
    const float* txt  = (const float*)d_in[1];
    const int*   key  = (const int*)d_in[2];
    const float* logt = (const float*)d_in[3];
    const float* bias = (const float*)d_in[4];

    float* out      = (float*)d_out;
    float* out_loss = out;                                   // [1]
    float* out_sel  = out + 1;                               // [4096]
    float* out_zimg = out_sel + N_TXT;                       // [16384*512]
    float* out_ztxt = out_zimg + (size_t)S_IMG * DIM;        // [4096*512]
    float* out_ap   = out_ztxt + (size_t)N_TXT * DIM;        // [16384*4096]
    float* out_fl   = out_ap + (size_t)S_IMG * N_TXT;        // [4096*4096]

    cudaFuncSetAttribute(gemm_kernel, cudaFuncAttributeMaxDynamicSharedMemorySize, GSMEM_BYTES);

    // normalize all rows (txt rows also init segmin/sel/rowsum)
    norm_all_kernel<<<S_IMG + N_TXT, 128>>>(img, txt, out_zimg, out_ztxt);

    // exact fp32 selection chain (now feeds the GEMM epilogue scatter)
    tp_kernel<<<S_IMG / 8, 256>>>(out_zimg, out_ztxt, key, logt, bias);
    pick_kernel<<<S_IMG / 256, 256>>>(key);

    // fork: index output + invalid-row FL fill run concurrently with the GEMM
    cudaEventRecord(g_fork, 0);
    cudaStreamWaitEvent(g_side, g_fork, 0);
    sel_kernel<<<(N_TXT + 255) / 256, 256, 0, g_side>>>(out_sel);
    fl_fill_kernel<<<N_TXT, 256, 0, g_side>>>(out_fl, bias);
    cudaEventRecord(g_join, g_side);

    // big GEMM: all_pairs + fused FL scatter + softplus partials
    gemm_kernel<<<dim3(N_TXT / BN, S_IMG / BM), 256, GSMEM_BYTES>>>(out_ap, out_fl, key, logt, bias);

    cudaStreamWaitEvent(0, g_join, 0);
    finalize_kernel<<<1, 256>>>(out_loss);
}

// round 16
// speedup vs baseline: 1.1458x; 1.0053x over previous
#include <cuda_runtime.h>
#include <cuda_fp16.h>
#include <cstdint>
#include <math.h>

#define S_IMG 16384
#define N_TXT 4096
#define DIM   512

// ---------------- scratch (static device globals; no allocations) ----------------
__device__ __half g_zimg_h[(size_t)S_IMG * DIM];  // fp16 zimg
__device__ __half g_ztxt_h[(size_t)N_TXT * DIM];  // fp16 ztxt
__device__ unsigned long long g_packed[N_TXT];    // (loss_bits<<32)|img_idx, atomicMin
__device__ float  g_rowsum[N_TXT];

// ---------------- streams/events: created at program load; reused every call ----
static cudaStream_t g_side;
static cudaEvent_t  g_fork, g_join;
struct _StreamInit {
    _StreamInit() {
        cudaStreamCreateWithFlags(&g_side, cudaStreamNonBlocking);
        cudaEventCreateWithFlags(&g_fork, cudaEventDisableTiming);
        cudaEventCreateWithFlags(&g_join, cudaEventDisableTiming);
    }
};
static _StreamInit g_si;

__global__ void init_kernel() {
    int i = blockIdx.x * blockDim.x + threadIdx.x;
    if (i < N_TXT) { g_packed[i] = ~0ull; g_rowsum[i] = 0.f; }
}

// ---------------- L2 normalize (img+txt, ONE launch) + FUSED true-positive ------
// img blocks: normalize own row (exact fp32 to d_out, fp16 to scratch), then
// re-normalize txt[key[row]] locally and compute tp loss -> packed atomicMin.
// txt blocks: normalize only.
__global__ void norm_all_kernel(const float* __restrict__ img, const float* __restrict__ txt,
                                const int* __restrict__ key,
                                float* __restrict__ dimg, float* __restrict__ dtxt,
                                const float* __restrict__ logt, const float* __restrict__ bias) {
    int row = blockIdx.x;
    int tid = threadIdx.x;  // 128 threads, each one float4 (512 elems)
    bool istxt = row >= S_IMG;
    const float* src;
    float* dst;
    __half* dst_h;
    int k = 0;
    float4 w = make_float4(0.f, 0.f, 0.f, 0.f);
    if (istxt) {
        row -= S_IMG;
        src = txt; dst = dtxt; dst_h = g_ztxt_h;
    } else {
        src = img; dst = dimg; dst_h = g_zimg_h;
        k = key[row];
        w = reinterpret_cast<const float4*>(txt + (size_t)k * DIM)[tid];
    }
    float4 v = reinterpret_cast<const float4*>(src + (size_t)row * DIM)[tid];
    float p = v.x * v.x + v.y * v.y + v.z * v.z + v.w * v.w;
    float q = w.x * w.x + w.y * w.y + w.z * w.z + w.w * w.w;
#pragma unroll
    for (int o = 16; o; o >>= 1) {
        p += __shfl_down_sync(0xffffffffu, p, o);
        q += __shfl_down_sync(0xffffffffu, q, o);
    }
    __shared__ float ws[4], qs[4];
    __shared__ float nshared, qshared;
    if ((tid & 31) == 0) { ws[tid >> 5] = p; qs[tid >> 5] = q; }
    __syncthreads();
    if (tid == 0) {
        nshared = sqrtf(ws[0] + ws[1] + ws[2] + ws[3]) + 1e-12f;
        qshared = sqrtf(qs[0] + qs[1] + qs[2] + qs[3]) + 1e-12f;
    }
    __syncthreads();
    float n = nshared;
    float4 o;
    o.x = v.x / n; o.y = v.y / n; o.z = v.z / n; o.w = v.w / n;
    float* drow = dst + (size_t)row * DIM + tid * 4;  // d_out only 4B-aligned
    drow[0] = o.x; drow[1] = o.y; drow[2] = o.z; drow[3] = o.w;
    __half2* hp = reinterpret_cast<__half2*>(dst_h + (size_t)row * DIM);
    hp[tid * 2]     = __floats2half2_rn(o.x, o.y);
    hp[tid * 2 + 1] = __floats2half2_rn(o.z, o.w);

    if (!istxt) {
        float qn = qshared;
        float d = (o.x * (w.x / qn)) + (o.y * (w.y / qn)) + (o.z * (w.z / qn)) + (o.w * (w.w / qn));
#pragma unroll
        for (int of = 16; of; of >>= 1) d += __shfl_down_sync(0xffffffffu, d, of);
        __shared__ float ds[4];
        if ((tid & 31) == 0) ds[tid >> 5] = d;
        __syncthreads();
        if (tid == 0) {
            float dot = ds[0] + ds[1] + ds[2] + ds[3];
            float t = expf(logt[0]);
            float tpl = fmaf(dot, t, bias[0]);
            float x = -tpl;
            float loss = fmaxf(x, 0.f) + log1pf(expf(-fabsf(x)));  // >= 0
            unsigned long long pk =
                ((unsigned long long)__float_as_uint(loss) << 32) | (unsigned)row;
            atomicMin(&g_packed[k], pk);  // min loss, then min index (exact-tie)
        }
    }
}

// out_sel from packed (side stream, hidden under GEMM) ---------------------------
__global__ void sel_kernel(float* __restrict__ out_idx) {
    int j = blockIdx.x * blockDim.x + threadIdx.x;
    if (j < N_TXT) {
        uint32_t low = (uint32_t)g_packed[j];
        out_idx[j] = (low < S_IMG) ? (float)low : -1.0f;
    }
}

// fill FL rows for invalid (empty-segment) texts with bias; set their rowsum ------
__global__ void fl_fill_kernel(float* __restrict__ FL, const float* __restrict__ bias) {
    int j = blockIdx.x;
    if ((uint32_t)g_packed[j] < S_IMG) return;
    float bb = bias[0];
    float* dst = FL + (size_t)j * N_TXT;
    for (int c = threadIdx.x; c < N_TXT; c += blockDim.x) dst[c] = bb;
    if (threadIdx.x == 0) {
        float sp_n = fmaxf(-bb, 0.f) + log1pf(expf(-fabsf(bb)));
        float sp_p = fmaxf(bb, 0.f) + log1pf(expf(-fabsf(bb)));
        g_rowsum[j] = sp_n + 4095.0f * sp_p;
    }
}

// ---------------- fp16 mma.sync GEMM (R13 core + fused FL scatter epilogue) ------
#define BM 128
#define BN 128
#define BKH 64                                  // fp16 k per stage
#define NSTG (DIM / BKH)                        // 8
#define NBUF 3
#define LDHB 144                                // bytes per smem row (64 fp16 + 8 pad)
#define AREG (BM * LDHB)                        // 18432
#define STAGE_BYTES (2 * AREG)                  // 36864 (A + B)
#define GSMEM_BYTES (NBUF * STAGE_BYTES)        // 110592; 2 CTAs = 216KB <= 228KB

__device__ __forceinline__ uint32_t smem_u32(const void* p) {
    uint32_t a;
    asm("{ .reg .u64 t; cvta.to.shared.u64 t, %1; cvt.u32.u64 %0, t; }" : "=r"(a) : "l"(p));
    return a;
}
__device__ __forceinline__ void cp16(void* s, const void* g) {
    uint32_t sa = smem_u32(s);
    asm volatile("cp.async.cg.shared.global [%0], [%1], 16;\n" ::"r"(sa), "l"(g) : "memory");
}
#define LDSM4(r0, r1, r2, r3, addr)                                            \
    asm volatile("ldmatrix.sync.aligned.m8n8.x4.shared.b16 {%0,%1,%2,%3}, [%4];" \
                 : "=r"(r0), "=r"(r1), "=r"(r2), "=r"(r3) : "r"(addr))

__device__ __forceinline__ void mmaf16(float* d, const uint32_t* a, const uint32_t* b) {
    asm volatile(
        "mma.sync.aligned.m16n8k16.row.col.f32.f16.f16.f32 "
        "{%0,%1,%2,%3}, {%4,%5,%6,%7}, {%8,%9}, {%0,%1,%2,%3};\n"
        : "+f"(d[0]), "+f"(d[1]), "+f"(d[2]), "+f"(d[3])
        : "r"(a[0]), "r"(a[1]), "r"(a[2]), "r"(a[3]), "r"(b[0]), "r"(b[1]));
}

__global__ __launch_bounds__(256, 2) void gemm_kernel(float* __restrict__ C,
                                                      float* __restrict__ FL,
                                                      const int* __restrict__ key,
                                                      const float* __restrict__ logt,
                                                      const float* __restrict__ bias) {
    extern __shared__ __align__(128) char smem[];
    uint32_t sb = smem_u32(smem);
    const __half* A = g_zimg_h;
    const __half* B = g_ztxt_h;
    int tid = threadIdx.x;
    int lane = tid & 31, warp = tid >> 5;
    int wm = warp >> 1, wn = warp & 1;  // 4x2 warp grid; warp tile 32x64
    size_t m0 = (size_t)blockIdx.y * BM;
    size_t n0 = (size_t)blockIdx.x * BN;

    float acc[2][8][4];
#pragma unroll
    for (int i = 0; i < 2; i++)
#pragma unroll
        for (int j = 0; j < 8; j++)
#pragma unroll
            for (int r = 0; r < 4; r++) acc[i][j][r] = 0.f;

    auto load_stage = [&](int s, int buf) {
        char* st = smem + buf * STAGE_BYTES;
        int kof = s * BKH;
#pragma unroll
        for (int i = 0; i < 4; i++) {
            int e = tid + i * 256;
            int r = e >> 3, c = e & 7;
            cp16(st + r * LDHB + c * 16, A + (m0 + r) * DIM + kof + c * 8);
        }
        char* stb = st + AREG;
#pragma unroll
        for (int i = 0; i < 4; i++) {
            int e = tid + i * 256;
            int r = e >> 3, c = e & 7;
            cp16(stb + r * LDHB + c * 16, B + (n0 + r) * DIM + kof + c * 8);
        }
        asm volatile("cp.async.commit_group;\n" ::: "memory");
    };

    load_stage(0, 0);
    load_stage(1, 1);

    int lrow = lane & 7;
    int aRow = ((lane >> 3) & 1) * 8 + lrow;
    int aColB = (lane >> 4) * 16;
    int bRow = (lane >> 4) * 8 + lrow;
    int bColB = ((lane >> 3) & 1) * 16;

    uint32_t af[2][2][4], bf[2][8][2];  // register fragment double buffers

#pragma unroll
    for (int kt = 0; kt < NSTG; kt++) {
        const int buf = kt % NBUF;
        if (kt < NSTG - 1) asm volatile("cp.async.wait_group 1;" ::: "memory");
        else               asm volatile("cp.async.wait_group 0;" ::: "memory");
        __syncthreads();  // single barrier per stage

        if (kt + 2 < NSTG) load_stage(kt + 2, (kt + 2) % NBUF);

        uint32_t base = sb + buf * STAGE_BYTES;
        uint32_t baseA = base + (wm * 32 + aRow) * LDHB + aColB;
        uint32_t baseB = base + AREG + (wn * 64 + bRow) * LDHB + bColB;

#pragma unroll
        for (int mi = 0; mi < 2; mi++)
            LDSM4(af[0][mi][0], af[0][mi][1], af[0][mi][2], af[0][mi][3],
                  baseA + mi * 16 * LDHB);
#pragma unroll
        for (int p = 0; p < 4; p++)
            LDSM4(bf[0][2 * p][0], bf[0][2 * p][1], bf[0][2 * p + 1][0], bf[0][2 * p + 1][1],
                  baseB + p * 16 * LDHB);

#pragma unroll
        for (int ks = 0; ks < BKH / 16; ks++) {
            int cur = ks & 1, nxt = cur ^ 1;
            if (ks < BKH / 16 - 1) {
                uint32_t kb = (ks + 1) * 32;
#pragma unroll
                for (int mi = 0; mi < 2; mi++)
                    LDSM4(af[nxt][mi][0], af[nxt][mi][1], af[nxt][mi][2], af[nxt][mi][3],
                          baseA + mi * 16 * LDHB + kb);
#pragma unroll
                for (int p = 0; p < 4; p++)
                    LDSM4(bf[nxt][2 * p][0], bf[nxt][2 * p][1],
                          bf[nxt][2 * p + 1][0], bf[nxt][2 * p + 1][1],
                          baseB + p * 16 * LDHB + kb);
            }
#pragma unroll
            for (int mi = 0; mi < 2; mi++)
#pragma unroll
                for (int ni = 0; ni < 8; ni++) mmaf16(acc[mi][ni], af[cur][mi], bf[cur][ni]);
        }
    }

    // epilogue: store AP; for selected rows ((u32)g_packed[key[r]] == r, injective)
    // scatter into FL[j,:] and accumulate softplus partial row-sums.
    float t = expf(logt[0]);
    float bb = bias[0];
#pragma unroll
    for (int mi = 0; mi < 2; mi++)
#pragma unroll
        for (int half = 0; half < 2; half++) {
            size_t row = m0 + wm * 32 + mi * 16 + (lane >> 2) + half * 8;
            int j = key[row];
            bool selrow = ((uint32_t)g_packed[j] == (uint32_t)row);
            float lsum = 0.f;
#pragma unroll
            for (int ni = 0; ni < 8; ni++) {
                size_t col = n0 + wn * 64 + ni * 8 + (size_t)(lane & 3) * 2;
                float v0 = fmaf(acc[mi][ni][half * 2 + 0], t, bb);
                float v1 = fmaf(acc[mi][ni][half * 2 + 1], t, bb);
                float* p = C + row * N_TXT + col;   // scalar: d_out 4B-aligned
                p[0] = v0;
                p[1] = v1;
                if (selrow) {
                    float* q = FL + (size_t)j * N_TXT + col;
                    q[0] = v0;
                    q[1] = v1;
                    float z0 = ((int)col == j) ? -v0 : v0;
                    float z1 = ((int)col + 1 == j) ? -v1 : v1;
                    lsum += fmaxf(z0, 0.f) + __logf(1.f + __expf(-fabsf(z0)));
                    lsum += fmaxf(z1, 0.f) + __logf(1.f + __expf(-fabsf(z1)));
                }
            }
            if (selrow) atomicAdd(&g_rowsum[j], lsum);
        }
}

__global__ void finalize_kernel(float* __restrict__ out) {
    int tid = threadIdx.x;
    double s = 0.0;
    for (int i = tid; i < N_TXT; i += 256) s += (double)g_rowsum[i];
#pragma unroll
    for (int o = 16; o; o >>= 1) s += __shfl_down_sync(0xffffffffu, s, o);
    __shared__ double sm[8];
    if ((tid & 31) == 0) sm[tid >> 5] = s;
    __syncthreads();
    if (tid == 0) {
        double tot = 0.0;
#pragma unroll
        for (int w = 0; w < 8; w++) tot += sm[w];
        out[0] = (float)(tot / (double)N_TXT);
    }
}

// ---------------- launch ---------------------------------------------------------
extern "C" void kernel_launch(void* const* d_in, const int* in_sizes, int n_in,
                              void* d_out, int out_size) {
    const float* img  = (const float*)d_in[0];
    const float* txt  = (const float*)d_in[1];
    const int*   key  = (const int*)d_in[2];
    const float* logt = (const float*)d_in[3];
    const float* bias = (const float*)d_in[4];

    float* out      = (float*)d_out;
    float* out_loss = out;                                   // [1]
    float* out_sel  = out + 1;                               // [4096]
    float* out_zimg = out_sel + N_TXT;                       // [16384*512]
    float* out_ztxt = out_zimg + (size_t)S_IMG * DIM;        // [4096*512]
    float* out_ap   = out_ztxt + (size_t)N_TXT * DIM;        // [16384*4096]
    float* out_fl   = out_ap + (size_t)S_IMG * N_TXT;        // [4096*4096]

    cudaFuncSetAttribute(gemm_kernel, cudaFuncAttributeMaxDynamicSharedMemorySize, GSMEM_BYTES);

    // init packed/rowsum (must precede fused atomicMin in norm)
    init_kernel<<<(N_TXT + 255) / 256, 256>>>();

    // normalize all rows + fused true-positive selection (packed 64-bit atomicMin)
    norm_all_kernel<<<S_IMG + N_TXT, 128>>>(img, txt, key, out_zimg, out_ztxt, logt, bias);

    // fork: index output + invalid-row FL fill run concurrently with the GEMM
    cudaEventRecord(g_fork, 0);
    cudaStreamWaitEvent(g_side, g_fork, 0);
    sel_kernel<<<(N_TXT + 255) / 256, 256, 0, g_side>>>(out_sel);
    fl_fill_kernel<<<N_TXT, 256, 0, g_side>>>(out_fl, bias);
    cudaEventRecord(g_join, g_side);

    // big GEMM: all_pairs + fused FL scatter + softplus partials
    gemm_kernel<<<dim3(N_TXT / BN, S_IMG / BM), 256, GSMEM_BYTES>>>(out_ap, out_fl, key, logt, bias);

    cudaStreamWaitEvent(0, g_join, 0);
    finalize_kernel<<<1, 256>>>(out_loss);
}